// round 1
// baseline (speedup 1.0000x reference)
#include <cuda_runtime.h>
#include <math.h>

#define N_NODES   40000
#define N_EDGES   640000
#define FDIM      128
#define N_GRAPHS  64
#define N_CLASSES 10

// ---------------- scratch (device globals; no allocations allowed) ----------
__device__ float g_bufB[N_NODES * FDIM];   // gemm output (h = x @ W)
__device__ float g_bufC[N_NODES * FDIM];   // aggregation accumulator
__device__ float g_bufA[N_NODES * FDIM];   // post bias+relu features
__device__ float g_deg[N_NODES];
__device__ float g_norm[N_EDGES];
__device__ float g_sums[N_GRAPHS * FDIM];
__device__ float g_cnts[N_GRAPHS];

// ---------------- degree / norm precompute ---------------------------------
__global__ void deg_init_kernel() {
    int i = blockIdx.x * blockDim.x + threadIdx.x;
    if (i < N_NODES) g_deg[i] = 1.0f;   // self-loop weight
}

__global__ void deg_count_kernel(const int* __restrict__ col) {
    int e = blockIdx.x * blockDim.x + threadIdx.x;
    if (e < N_EDGES) atomicAdd(&g_deg[col[e]], 1.0f);
}

__global__ void norm_kernel(const int* __restrict__ row, const int* __restrict__ col) {
    int e = blockIdx.x * blockDim.x + threadIdx.x;
    if (e < N_EDGES) {
        float dr = rsqrtf(g_deg[row[e]]);
        float dc = rsqrtf(g_deg[col[e]]);
        g_norm[e] = dr * dc;
    }
}

// ---------------- GEMM: Y[n,128] = X[n,128] @ W[128,128] -------------------
// Block: 256 threads (8 warps). Tile: 64 rows x 128 cols.
// Warp w computes rows [w*8, w*8+8); lane handles 4 consecutive cols.
#define GEMM_BM 64
__global__ void gemm128_kernel(const float* __restrict__ X,
                               const float* __restrict__ W,
                               float* __restrict__ Y, int nrows) {
    extern __shared__ float sm[];
    float* Ws = sm;                 // 128*128 floats (64 KB)
    float* Xs = sm + 128 * 128;     // 64*128 floats  (32 KB)

    int tid  = threadIdx.x;
    int row0 = blockIdx.x * GEMM_BM;

    // load W (4096 float4 / 256 threads = 16 each)
    const float4* W4  = (const float4*)W;
    float4*       Ws4 = (float4*)Ws;
#pragma unroll
    for (int i = 0; i < 16; i++) Ws4[tid + 256 * i] = W4[tid + 256 * i];

    // load X tile (2048 float4 / 256 threads = 8 each)
    const float4* X4  = (const float4*)(X + (size_t)row0 * FDIM);
    float4*       Xs4 = (float4*)Xs;
    int nvalid = nrows - row0; if (nvalid > GEMM_BM) nvalid = GEMM_BM;
    int maxv4 = nvalid * 32;
#pragma unroll
    for (int i = 0; i < 8; i++) {
        int idx = tid + 256 * i;
        if (idx < maxv4) Xs4[idx] = X4[idx];
    }
    __syncthreads();

    int warp = tid >> 5, lane = tid & 31;
    int rbase = warp * 8;

    float4 acc[8];
#pragma unroll
    for (int r = 0; r < 8; r++) acc[r] = make_float4(0.f, 0.f, 0.f, 0.f);

#pragma unroll 4
    for (int k = 0; k < 128; k++) {
        float4 wv = Ws4[k * 32 + lane];
#pragma unroll
        for (int r = 0; r < 8; r++) {
            float xv = Xs[(rbase + r) * 128 + k];
            acc[r].x = fmaf(wv.x, xv, acc[r].x);
            acc[r].y = fmaf(wv.y, xv, acc[r].y);
            acc[r].z = fmaf(wv.z, xv, acc[r].z);
            acc[r].w = fmaf(wv.w, xv, acc[r].w);
        }
    }

#pragma unroll
    for (int r = 0; r < 8; r++) {
        int row = row0 + rbase + r;
        if (row < nrows)
            ((float4*)(Y + (size_t)row * FDIM))[lane] = acc[r];
    }
}

// ---------------- self-loop init: C[i,:] = B[i,:] / deg[i] -----------------
__global__ void init_agg_kernel() {
    int idx = blockIdx.x * blockDim.x + threadIdx.x;   // over N_NODES*32 float4s
    if (idx >= N_NODES * 32) return;
    int node = idx >> 5;
    float inv = 1.0f / g_deg[node];
    float4 v = ((const float4*)g_bufB)[idx];
    v.x *= inv; v.y *= inv; v.z *= inv; v.w *= inv;
    ((float4*)g_bufC)[idx] = v;
}

// ---------------- edge scatter: C[col] += B[row] * norm --------------------
// One warp per edge: 1 coalesced 512B gather + 32x red.global.add.v4.f32
__global__ void scatter_kernel(const int* __restrict__ row,
                               const int* __restrict__ col) {
    int e = blockIdx.x * (blockDim.x >> 5) + (threadIdx.x >> 5);
    if (e >= N_EDGES) return;
    int lane = threadIdx.x & 31;

    int   r  = __ldg(&row[e]);
    int   c  = __ldg(&col[e]);
    float nv = __ldg(&g_norm[e]);

    float4 v = ((const float4*)(g_bufB + (size_t)r * FDIM))[lane];
    v.x *= nv; v.y *= nv; v.z *= nv; v.w *= nv;

    float* dst = g_bufC + (size_t)c * FDIM + lane * 4;
    asm volatile("red.global.add.v4.f32 [%0], {%1, %2, %3, %4};"
                 :: "l"(dst), "f"(v.x), "f"(v.y), "f"(v.z), "f"(v.w)
                 : "memory");
}

// ---------------- bias + relu: A = relu(C + b) ------------------------------
__global__ void bias_relu_kernel(const float* __restrict__ b) {
    int idx = blockIdx.x * blockDim.x + threadIdx.x;   // N_NODES*32 float4s
    if (idx >= N_NODES * 32) return;
    float4 bv = __ldg(&((const float4*)b)[idx & 31]);
    float4 v  = ((const float4*)g_bufC)[idx];
    v.x = fmaxf(v.x + bv.x, 0.f);
    v.y = fmaxf(v.y + bv.y, 0.f);
    v.z = fmaxf(v.z + bv.z, 0.f);
    v.w = fmaxf(v.w + bv.w, 0.f);
    ((float4*)g_bufA)[idx] = v;
}

// ---------------- pooling ----------------------------------------------------
__global__ void zero_pool_kernel() {
    int i = threadIdx.x;
    for (int k = i; k < N_GRAPHS * FDIM; k += blockDim.x) g_sums[k] = 0.f;
    if (i < N_GRAPHS) g_cnts[i] = 0.f;
}

__global__ void pool_kernel(const int* __restrict__ batch) {
    int node = blockIdx.x * (blockDim.x >> 5) + (threadIdx.x >> 5);
    if (node >= N_NODES) return;
    int lane = threadIdx.x & 31;
    int g = __ldg(&batch[node]);
    float4 v = ((const float4*)(g_bufA + (size_t)node * FDIM))[lane];
    float* dst = g_sums + (size_t)g * FDIM + lane * 4;
    asm volatile("red.global.add.v4.f32 [%0], {%1, %2, %3, %4};"
                 :: "l"(dst), "f"(v.x), "f"(v.y), "f"(v.z), "f"(v.w)
                 : "memory");
    if (lane == 0) atomicAdd(&g_cnts[g], 1.0f);
}

// ---------------- final linear: out[g, c] = pooled[g] @ Wl + bl -------------
__global__ void final_kernel(const float* __restrict__ Wl,
                             const float* __restrict__ bl,
                             float* __restrict__ out) {
    int g = blockIdx.x;          // one block per graph, 32 threads
    int c = threadIdx.x;
    if (c >= N_CLASSES) return;
    float cnt = g_cnts[g];
    float inv = 1.0f / fmaxf(cnt, 1.0f);
    float acc = bl[c];
    for (int k = 0; k < FDIM; k++)
        acc += (g_sums[g * FDIM + k] * inv) * Wl[k * N_CLASSES + c];
    out[g * N_CLASSES + c] = acc;
}

// ---------------- launch ----------------------------------------------------
extern "C" void kernel_launch(void* const* d_in, const int* in_sizes, int n_in,
                              void* d_out, int out_size) {
    const float* x   = (const float*)d_in[0];
    const int*   ei  = (const int*)d_in[1];       // [2, E]: row then col
    const int*   bat = (const int*)d_in[2];
    const float* W1  = (const float*)d_in[3];
    const float* b1  = (const float*)d_in[4];
    const float* W2  = (const float*)d_in[5];
    const float* b2  = (const float*)d_in[6];
    const float* W3  = (const float*)d_in[7];
    const float* b3  = (const float*)d_in[8];
    const float* Wl  = (const float*)d_in[9];
    const float* bl  = (const float*)d_in[10];
    float* out = (float*)d_out;

    const int* row = ei;
    const int* col = ei + N_EDGES;

    static bool attr_set = false;
    if (!attr_set) {
        cudaFuncSetAttribute(gemm128_kernel,
                             cudaFuncAttributeMaxDynamicSharedMemorySize,
                             (128 * 128 + GEMM_BM * 128) * (int)sizeof(float));
        attr_set = true;
    }
    const int GEMM_SMEM = (128 * 128 + GEMM_BM * 128) * (int)sizeof(float);

    // norm precompute
    deg_init_kernel<<<(N_NODES + 255) / 256, 256>>>();
    deg_count_kernel<<<(N_EDGES + 255) / 256, 256>>>(col);
    norm_kernel<<<(N_EDGES + 255) / 256, 256>>>(row, col);

    const int elem_blocks = (N_NODES * 32 + 255) / 256;
    const int gemm_blocks = (N_NODES + GEMM_BM - 1) / GEMM_BM;
    const int edge_warp_blocks = (N_EDGES + 7) / 8;    // 8 warps / 256-thr block
    const int node_warp_blocks = (N_NODES + 7) / 8;

    const float* feat_in = x;
    const float* biases[3] = {b1, b2, b3};
    const float* weights[3] = {W1, W2, W3};

    for (int l = 0; l < 3; l++) {
        float* B; cudaGetSymbolAddress((void**)&B, g_bufB); // resolves immediately
        gemm128_kernel<<<gemm_blocks, 256, GEMM_SMEM>>>(feat_in, weights[l], B, N_NODES);
        init_agg_kernel<<<elem_blocks, 256>>>();
        scatter_kernel<<<edge_warp_blocks, 256>>>(row, col);
        bias_relu_kernel<<<elem_blocks, 256>>>(biases[l]);
        float* A; cudaGetSymbolAddress((void**)&A, g_bufA);
        feat_in = A;
    }

    zero_pool_kernel<<<1, 256>>>();
    pool_kernel<<<node_warp_blocks, 256>>>(bat);
    final_kernel<<<N_GRAPHS, 32>>>(Wl, bl, out);
}

// round 2
// speedup vs baseline: 1.4954x; 1.4954x over previous
#include <cuda_runtime.h>
#include <math.h>

#define N_NODES   40000
#define N_EDGES   640000
#define FDIM      128
#define N_GRAPHS  64
#define N_CLASSES 10

#define SCAN_B    1024
#define SCAN_NB   ((N_NODES + SCAN_B - 1) / SCAN_B)   // 40

// ---------------- scratch (device globals; no allocations) ------------------
__device__ float g_bufB[N_NODES * FDIM];   // gemm output (h = x @ W)
__device__ float g_bufA[N_NODES * FDIM];   // post aggregate+bias+relu features
__device__ int   g_indeg[N_NODES];         // in-degree (excl. self loop)
__device__ float g_dis[N_NODES];           // rsqrt(deg) incl. self loop
__device__ int   g_off[N_NODES];           // CSR offsets (exclusive scan)
__device__ int   g_cursor[N_NODES];        // fill cursors
__device__ int   g_bsum[SCAN_NB];          // block sums for scan
__device__ int2  g_srcwt[N_EDGES];         // CSR payload: (src row, norm as bits)
__device__ float g_sums[N_GRAPHS * FDIM];
__device__ float g_cnts[N_GRAPHS];

// ---------------- degree ----------------------------------------------------
__global__ void deg_init_kernel() {
    int i = blockIdx.x * blockDim.x + threadIdx.x;
    if (i < N_NODES) g_indeg[i] = 0;
}

__global__ void deg_count_kernel(const int* __restrict__ col) {
    int e = blockIdx.x * blockDim.x + threadIdx.x;
    if (e < N_EDGES) atomicAdd(&g_indeg[col[e]], 1);
}

__global__ void dis_kernel() {
    int i = blockIdx.x * blockDim.x + threadIdx.x;
    if (i < N_NODES) g_dis[i] = rsqrtf((float)(g_indeg[i] + 1));
}

// ---------------- exclusive scan of g_indeg -> g_off ------------------------
__global__ void scanA_kernel() {
    __shared__ int s[SCAN_B];
    int tid = threadIdx.x;
    int gid = blockIdx.x * SCAN_B + tid;
    int v = (gid < N_NODES) ? g_indeg[gid] : 0;
    s[tid] = v;
    __syncthreads();
#pragma unroll
    for (int off = 1; off < SCAN_B; off <<= 1) {
        int t = 0;
        if (tid >= off) t = s[tid - off];
        __syncthreads();
        if (tid >= off) s[tid] += t;
        __syncthreads();
    }
    if (gid < N_NODES) g_off[gid] = s[tid] - v;       // exclusive
    if (tid == SCAN_B - 1) g_bsum[blockIdx.x] = s[tid];
}

__global__ void scanB_kernel() {
    if (threadIdx.x == 0) {
        int run = 0;
        for (int i = 0; i < SCAN_NB; i++) {
            int t = g_bsum[i];
            g_bsum[i] = run;
            run += t;
        }
    }
}

__global__ void scanC_kernel() {
    int gid = blockIdx.x * SCAN_B + threadIdx.x;
    if (gid < N_NODES) {
        int o = g_off[gid] + g_bsum[blockIdx.x];
        g_off[gid] = o;
        g_cursor[gid] = o;
    }
}

// ---------------- CSR fill ---------------------------------------------------
__global__ void fill_kernel(const int* __restrict__ row,
                            const int* __restrict__ col) {
    int e = blockIdx.x * blockDim.x + threadIdx.x;
    if (e >= N_EDGES) return;
    int r = row[e];
    int c = col[e];
    int p = atomicAdd(&g_cursor[c], 1);
    float w = g_dis[r] * g_dis[c];
    g_srcwt[p] = make_int2(r, __float_as_int(w));
}

// ---------------- GEMM: Y[n,128] = X[n,128] @ W[128,128] -------------------
#define GEMM_BM 64
__global__ void gemm128_kernel(const float* __restrict__ X,
                               const float* __restrict__ W,
                               float* __restrict__ Y, int nrows) {
    extern __shared__ float sm[];
    float* Ws = sm;                 // 128*128 floats (64 KB)
    float* Xs = sm + 128 * 128;     // 64*128 floats  (32 KB)

    int tid  = threadIdx.x;
    int row0 = blockIdx.x * GEMM_BM;

    const float4* W4  = (const float4*)W;
    float4*       Ws4 = (float4*)Ws;
#pragma unroll
    for (int i = 0; i < 16; i++) Ws4[tid + 256 * i] = W4[tid + 256 * i];

    const float4* X4  = (const float4*)(X + (size_t)row0 * FDIM);
    float4*       Xs4 = (float4*)Xs;
    int nvalid = nrows - row0; if (nvalid > GEMM_BM) nvalid = GEMM_BM;
    int maxv4 = nvalid * 32;
#pragma unroll
    for (int i = 0; i < 8; i++) {
        int idx = tid + 256 * i;
        if (idx < maxv4) Xs4[idx] = X4[idx];
    }
    __syncthreads();

    int warp = tid >> 5, lane = tid & 31;
    int rbase = warp * 8;

    float4 acc[8];
#pragma unroll
    for (int r = 0; r < 8; r++) acc[r] = make_float4(0.f, 0.f, 0.f, 0.f);

#pragma unroll 4
    for (int k = 0; k < 128; k++) {
        float4 wv = Ws4[k * 32 + lane];
#pragma unroll
        for (int r = 0; r < 8; r++) {
            float xv = Xs[(rbase + r) * 128 + k];
            acc[r].x = fmaf(wv.x, xv, acc[r].x);
            acc[r].y = fmaf(wv.y, xv, acc[r].y);
            acc[r].z = fmaf(wv.z, xv, acc[r].z);
            acc[r].w = fmaf(wv.w, xv, acc[r].w);
        }
    }

#pragma unroll
    for (int r = 0; r < 8; r++) {
        int row = row0 + rbase + r;
        if (row < nrows)
            ((float4*)(Y + (size_t)row * FDIM))[lane] = acc[r];
    }
}

// ---------------- CSR gather: A[n] = relu( sum_in + selfloop + bias ) -------
// One warp per node; register accumulators; single write per output row.
__global__ void gather_kernel(const float* __restrict__ bias) {
    int node = blockIdx.x * (blockDim.x >> 5) + (threadIdx.x >> 5);
    if (node >= N_NODES) return;
    int lane = threadIdx.x & 31;

    const float4* B4 = (const float4*)g_bufB;

    int beg = g_off[node];
    int end = beg + g_indeg[node];

    float dn = g_dis[node];
    float sl = dn * dn;                       // 1/deg self-loop weight
    float4 acc = B4[(size_t)node * 32 + lane];
    acc.x *= sl; acc.y *= sl; acc.z *= sl; acc.w *= sl;

    for (int i = beg; i < end; i++) {
        int2 ew = g_srcwt[i];                 // broadcast within warp
        float w = __int_as_float(ew.y);
        float4 v = B4[(size_t)ew.x * 32 + lane];
        acc.x = fmaf(w, v.x, acc.x);
        acc.y = fmaf(w, v.y, acc.y);
        acc.z = fmaf(w, v.z, acc.z);
        acc.w = fmaf(w, v.w, acc.w);
    }

    float4 bv = __ldg(&((const float4*)bias)[lane]);
    acc.x = fmaxf(acc.x + bv.x, 0.f);
    acc.y = fmaxf(acc.y + bv.y, 0.f);
    acc.z = fmaxf(acc.z + bv.z, 0.f);
    acc.w = fmaxf(acc.w + bv.w, 0.f);
    ((float4*)g_bufA)[(size_t)node * 32 + lane] = acc;
}

// ---------------- pooling ----------------------------------------------------
__global__ void zero_pool_kernel() {
    int i = threadIdx.x;
    for (int k = i; k < N_GRAPHS * FDIM; k += blockDim.x) g_sums[k] = 0.f;
    if (i < N_GRAPHS) g_cnts[i] = 0.f;
}

__global__ void pool_kernel(const int* __restrict__ batch) {
    int node = blockIdx.x * (blockDim.x >> 5) + (threadIdx.x >> 5);
    if (node >= N_NODES) return;
    int lane = threadIdx.x & 31;
    int g = __ldg(&batch[node]);
    float4 v = ((const float4*)g_bufA)[(size_t)node * 32 + lane];
    float* dst = g_sums + (size_t)g * FDIM + lane * 4;
    asm volatile("red.global.add.v4.f32 [%0], {%1, %2, %3, %4};"
                 :: "l"(dst), "f"(v.x), "f"(v.y), "f"(v.z), "f"(v.w)
                 : "memory");
    if (lane == 0) atomicAdd(&g_cnts[g], 1.0f);
}

// ---------------- final linear ----------------------------------------------
__global__ void final_kernel(const float* __restrict__ Wl,
                             const float* __restrict__ bl,
                             float* __restrict__ out) {
    int g = blockIdx.x;
    int c = threadIdx.x;
    if (c >= N_CLASSES) return;
    float cnt = g_cnts[g];
    float inv = 1.0f / fmaxf(cnt, 1.0f);
    float acc = bl[c];
    for (int k = 0; k < FDIM; k++)
        acc += (g_sums[g * FDIM + k] * inv) * Wl[k * N_CLASSES + c];
    out[g * N_CLASSES + c] = acc;
}

// ---------------- launch ----------------------------------------------------
extern "C" void kernel_launch(void* const* d_in, const int* in_sizes, int n_in,
                              void* d_out, int out_size) {
    const float* x   = (const float*)d_in[0];
    const int*   ei  = (const int*)d_in[1];       // [2, E]: row then col
    const int*   bat = (const int*)d_in[2];
    const float* W1  = (const float*)d_in[3];
    const float* b1  = (const float*)d_in[4];
    const float* W2  = (const float*)d_in[5];
    const float* b2  = (const float*)d_in[6];
    const float* W3  = (const float*)d_in[7];
    const float* b3  = (const float*)d_in[8];
    const float* Wl  = (const float*)d_in[9];
    const float* bl  = (const float*)d_in[10];
    float* out = (float*)d_out;

    const int* row = ei;
    const int* col = ei + N_EDGES;

    static bool attr_set = false;
    if (!attr_set) {
        cudaFuncSetAttribute(gemm128_kernel,
                             cudaFuncAttributeMaxDynamicSharedMemorySize,
                             (128 * 128 + GEMM_BM * 128) * (int)sizeof(float));
        attr_set = true;
    }
    const int GEMM_SMEM = (128 * 128 + GEMM_BM * 128) * (int)sizeof(float);

    // ---- norm + CSR build ----
    deg_init_kernel<<<(N_NODES + 255) / 256, 256>>>();
    deg_count_kernel<<<(N_EDGES + 255) / 256, 256>>>(col);
    dis_kernel<<<(N_NODES + 255) / 256, 256>>>();
    scanA_kernel<<<SCAN_NB, SCAN_B>>>();
    scanB_kernel<<<1, 32>>>();
    scanC_kernel<<<SCAN_NB, SCAN_B>>>();
    fill_kernel<<<(N_EDGES + 255) / 256, 256>>>(row, col);

    const int gemm_blocks = (N_NODES + GEMM_BM - 1) / GEMM_BM;
    const int node_warp_blocks = (N_NODES + 7) / 8;    // 8 warps / 256-thr block

    float* B; cudaGetSymbolAddress((void**)&B, g_bufB);
    float* A; cudaGetSymbolAddress((void**)&A, g_bufA);

    const float* feat_in = x;
    const float* biases[3]  = {b1, b2, b3};
    const float* weights[3] = {W1, W2, W3};

    for (int l = 0; l < 3; l++) {
        gemm128_kernel<<<gemm_blocks, 256, GEMM_SMEM>>>(feat_in, weights[l], B, N_NODES);
        gather_kernel<<<node_warp_blocks, 256>>>(biases[l]);
        feat_in = A;
    }

    zero_pool_kernel<<<1, 256>>>();
    pool_kernel<<<node_warp_blocks, 256>>>(bat);
    final_kernel<<<N_GRAPHS, 32>>>(Wl, bl, out);
}

// round 3
// speedup vs baseline: 1.6625x; 1.1117x over previous
#include <cuda_runtime.h>
#include <cuda_fp16.h>
#include <math.h>

#define N_NODES   40000
#define N_EDGES   640000
#define FDIM      128
#define N_GRAPHS  64
#define N_CLASSES 10

#define SCAN_B    1024
#define SCAN_NB   ((N_NODES + SCAN_B - 1) / SCAN_B)   // 40

// ---------------- scratch (device globals; no allocations) ------------------
__device__ __half g_B16[N_NODES * FDIM];   // gemm output (h = x @ W), fp16
__device__ float  g_bufA[N_NODES * FDIM];  // post aggregate+bias+relu (fp32)
__device__ int    g_indeg[N_NODES];        // in-degree (excl. self loop)
__device__ float  g_dis[N_NODES];          // rsqrt(deg) incl. self loop
__device__ int    g_off[N_NODES];          // CSR offsets (exclusive scan)
__device__ int    g_cursor[N_NODES];       // fill cursors
__device__ int    g_bsum[SCAN_NB];         // block sums for scan
__device__ int2   g_srcwt[N_EDGES];        // CSR payload: (src row, norm bits)
__device__ float  g_sums[N_GRAPHS * FDIM];
__device__ float  g_cnts[N_GRAPHS];

// ---------------- degree ----------------------------------------------------
__global__ void deg_init_kernel() {
    int i = blockIdx.x * blockDim.x + threadIdx.x;
    if (i < N_NODES) g_indeg[i] = 0;
}

__global__ void deg_count_kernel(const int* __restrict__ col) {
    int e = blockIdx.x * blockDim.x + threadIdx.x;
    if (e < N_EDGES) atomicAdd(&g_indeg[col[e]], 1);
}

__global__ void dis_kernel() {
    int i = blockIdx.x * blockDim.x + threadIdx.x;
    if (i < N_NODES) g_dis[i] = rsqrtf((float)(g_indeg[i] + 1));
}

// ---------------- exclusive scan of g_indeg -> g_off ------------------------
__global__ void scanA_kernel() {
    __shared__ int s[SCAN_B];
    int tid = threadIdx.x;
    int gid = blockIdx.x * SCAN_B + tid;
    int v = (gid < N_NODES) ? g_indeg[gid] : 0;
    s[tid] = v;
    __syncthreads();
#pragma unroll
    for (int off = 1; off < SCAN_B; off <<= 1) {
        int t = 0;
        if (tid >= off) t = s[tid - off];
        __syncthreads();
        if (tid >= off) s[tid] += t;
        __syncthreads();
    }
    if (gid < N_NODES) g_off[gid] = s[tid] - v;       // exclusive
    if (tid == SCAN_B - 1) g_bsum[blockIdx.x] = s[tid];
}

__global__ void scanB_kernel() {
    if (threadIdx.x == 0) {
        int run = 0;
        for (int i = 0; i < SCAN_NB; i++) {
            int t = g_bsum[i];
            g_bsum[i] = run;
            run += t;
        }
    }
}

__global__ void scanC_kernel() {
    int gid = blockIdx.x * SCAN_B + threadIdx.x;
    if (gid < N_NODES) {
        int o = g_off[gid] + g_bsum[blockIdx.x];
        g_off[gid] = o;
        g_cursor[gid] = o;
    }
}

// ---------------- CSR fill ---------------------------------------------------
__global__ void fill_kernel(const int* __restrict__ row,
                            const int* __restrict__ col) {
    int e = blockIdx.x * blockDim.x + threadIdx.x;
    if (e >= N_EDGES) return;
    int r = row[e];
    int c = col[e];
    int p = atomicAdd(&g_cursor[c], 1);
    float w = g_dis[r] * g_dis[c];
    g_srcwt[p] = make_int2(r, __float_as_int(w));
}

// ---------------- GEMM: Y16[n,128] = fp16( X[n,128] @ W[128,128] ) ----------
#define GEMM_BM 64
__global__ void gemm128_kernel(const float* __restrict__ X,
                               const float* __restrict__ W,
                               __half* __restrict__ Y16, int nrows) {
    extern __shared__ float sm[];
    float* Ws = sm;                 // 128*128 floats (64 KB)
    float* Xs = sm + 128 * 128;     // 64*128 floats  (32 KB)

    int tid  = threadIdx.x;
    int row0 = blockIdx.x * GEMM_BM;

    const float4* W4  = (const float4*)W;
    float4*       Ws4 = (float4*)Ws;
#pragma unroll
    for (int i = 0; i < 16; i++) Ws4[tid + 256 * i] = W4[tid + 256 * i];

    const float4* X4  = (const float4*)(X + (size_t)row0 * FDIM);
    float4*       Xs4 = (float4*)Xs;
    int nvalid = nrows - row0; if (nvalid > GEMM_BM) nvalid = GEMM_BM;
    int maxv4 = nvalid * 32;
#pragma unroll
    for (int i = 0; i < 8; i++) {
        int idx = tid + 256 * i;
        if (idx < maxv4) Xs4[idx] = X4[idx];
    }
    __syncthreads();

    int warp = tid >> 5, lane = tid & 31;
    int rbase = warp * 8;

    float4 acc[8];
#pragma unroll
    for (int r = 0; r < 8; r++) acc[r] = make_float4(0.f, 0.f, 0.f, 0.f);

#pragma unroll 4
    for (int k = 0; k < 128; k++) {
        float4 wv = Ws4[k * 32 + lane];
#pragma unroll
        for (int r = 0; r < 8; r++) {
            float xv = Xs[(rbase + r) * 128 + k];
            acc[r].x = fmaf(wv.x, xv, acc[r].x);
            acc[r].y = fmaf(wv.y, xv, acc[r].y);
            acc[r].z = fmaf(wv.z, xv, acc[r].z);
            acc[r].w = fmaf(wv.w, xv, acc[r].w);
        }
    }

#pragma unroll
    for (int r = 0; r < 8; r++) {
        int row = row0 + rbase + r;
        if (row < nrows) {
            __half2 h0 = __floats2half2_rn(acc[r].x, acc[r].y);
            __half2 h1 = __floats2half2_rn(acc[r].z, acc[r].w);
            uint2 u;
            u.x = *(unsigned int*)&h0;
            u.y = *(unsigned int*)&h1;
            ((uint2*)(Y16 + (size_t)row * FDIM))[lane] = u;
        }
    }
}

// ---------------- fp16 quad -> float4 ---------------------------------------
__device__ __forceinline__ float4 h4_to_f4(uint2 u) {
    __half2 a = *(__half2*)&u.x;
    __half2 b = *(__half2*)&u.y;
    float2 fa = __half22float2(a);
    float2 fb = __half22float2(b);
    return make_float4(fa.x, fa.y, fb.x, fb.y);
}

// ---------------- CSR gather: A[n] = relu( sum_in + selfloop + bias ) -------
// One warp per node; fp16 message reads (256B/row), fp32 accumulate.
__global__ void gather_kernel(const float* __restrict__ bias) {
    int node = blockIdx.x * (blockDim.x >> 5) + (threadIdx.x >> 5);
    if (node >= N_NODES) return;
    int lane = threadIdx.x & 31;

    const uint2* B2 = (const uint2*)g_B16;

    int beg = g_off[node];
    int end = beg + g_indeg[node];

    float dn = g_dis[node];
    float sl = dn * dn;                       // 1/deg self-loop weight
    float4 sv = h4_to_f4(B2[(size_t)node * 32 + lane]);
    float4 acc = make_float4(sv.x * sl, sv.y * sl, sv.z * sl, sv.w * sl);

    int i = beg;
    // 2-way unrolled for MLP
    for (; i + 2 <= end; i += 2) {
        int2 e0 = g_srcwt[i];
        int2 e1 = g_srcwt[i + 1];
        float w0 = __int_as_float(e0.y);
        float w1 = __int_as_float(e1.y);
        float4 v0 = h4_to_f4(B2[(size_t)e0.x * 32 + lane]);
        float4 v1 = h4_to_f4(B2[(size_t)e1.x * 32 + lane]);
        acc.x = fmaf(w0, v0.x, acc.x);
        acc.y = fmaf(w0, v0.y, acc.y);
        acc.z = fmaf(w0, v0.z, acc.z);
        acc.w = fmaf(w0, v0.w, acc.w);
        acc.x = fmaf(w1, v1.x, acc.x);
        acc.y = fmaf(w1, v1.y, acc.y);
        acc.z = fmaf(w1, v1.z, acc.z);
        acc.w = fmaf(w1, v1.w, acc.w);
    }
    if (i < end) {
        int2 e0 = g_srcwt[i];
        float w0 = __int_as_float(e0.y);
        float4 v0 = h4_to_f4(B2[(size_t)e0.x * 32 + lane]);
        acc.x = fmaf(w0, v0.x, acc.x);
        acc.y = fmaf(w0, v0.y, acc.y);
        acc.z = fmaf(w0, v0.z, acc.z);
        acc.w = fmaf(w0, v0.w, acc.w);
    }

    float4 bv = __ldg(&((const float4*)bias)[lane]);
    acc.x = fmaxf(acc.x + bv.x, 0.f);
    acc.y = fmaxf(acc.y + bv.y, 0.f);
    acc.z = fmaxf(acc.z + bv.z, 0.f);
    acc.w = fmaxf(acc.w + bv.w, 0.f);
    ((float4*)g_bufA)[(size_t)node * 32 + lane] = acc;
}

// ---------------- pooling ----------------------------------------------------
__global__ void zero_pool_kernel() {
    int i = threadIdx.x;
    for (int k = i; k < N_GRAPHS * FDIM; k += blockDim.x) g_sums[k] = 0.f;
    if (i < N_GRAPHS) g_cnts[i] = 0.f;
}

__global__ void pool_kernel(const int* __restrict__ batch) {
    int node = blockIdx.x * (blockDim.x >> 5) + (threadIdx.x >> 5);
    if (node >= N_NODES) return;
    int lane = threadIdx.x & 31;
    int g = __ldg(&batch[node]);
    float4 v = ((const float4*)g_bufA)[(size_t)node * 32 + lane];
    float* dst = g_sums + (size_t)g * FDIM + lane * 4;
    asm volatile("red.global.add.v4.f32 [%0], {%1, %2, %3, %4};"
                 :: "l"(dst), "f"(v.x), "f"(v.y), "f"(v.z), "f"(v.w)
                 : "memory");
    if (lane == 0) atomicAdd(&g_cnts[g], 1.0f);
}

// ---------------- final linear ----------------------------------------------
__global__ void final_kernel(const float* __restrict__ Wl,
                             const float* __restrict__ bl,
                             float* __restrict__ out) {
    int g = blockIdx.x;
    int c = threadIdx.x;
    if (c >= N_CLASSES) return;
    float cnt = g_cnts[g];
    float inv = 1.0f / fmaxf(cnt, 1.0f);
    float acc = bl[c];
    for (int k = 0; k < FDIM; k++)
        acc += (g_sums[g * FDIM + k] * inv) * Wl[k * N_CLASSES + c];
    out[g * N_CLASSES + c] = acc;
}

// ---------------- launch ----------------------------------------------------
extern "C" void kernel_launch(void* const* d_in, const int* in_sizes, int n_in,
                              void* d_out, int out_size) {
    const float* x   = (const float*)d_in[0];
    const int*   ei  = (const int*)d_in[1];       // [2, E]: row then col
    const int*   bat = (const int*)d_in[2];
    const float* W1  = (const float*)d_in[3];
    const float* b1  = (const float*)d_in[4];
    const float* W2  = (const float*)d_in[5];
    const float* b2  = (const float*)d_in[6];
    const float* W3  = (const float*)d_in[7];
    const float* b3  = (const float*)d_in[8];
    const float* Wl  = (const float*)d_in[9];
    const float* bl  = (const float*)d_in[10];
    float* out = (float*)d_out;

    const int* row = ei;
    const int* col = ei + N_EDGES;

    static bool attr_set = false;
    if (!attr_set) {
        cudaFuncSetAttribute(gemm128_kernel,
                             cudaFuncAttributeMaxDynamicSharedMemorySize,
                             (128 * 128 + GEMM_BM * 128) * (int)sizeof(float));
        attr_set = true;
    }
    const int GEMM_SMEM = (128 * 128 + GEMM_BM * 128) * (int)sizeof(float);

    // ---- norm + CSR build ----
    deg_init_kernel<<<(N_NODES + 255) / 256, 256>>>();
    deg_count_kernel<<<(N_EDGES + 255) / 256, 256>>>(col);
    dis_kernel<<<(N_NODES + 255) / 256, 256>>>();
    scanA_kernel<<<SCAN_NB, SCAN_B>>>();
    scanB_kernel<<<1, 32>>>();
    scanC_kernel<<<SCAN_NB, SCAN_B>>>();
    fill_kernel<<<(N_EDGES + 255) / 256, 256>>>(row, col);

    const int gemm_blocks = (N_NODES + GEMM_BM - 1) / GEMM_BM;
    const int node_warp_blocks = (N_NODES + 7) / 8;    // 8 warps / 256-thr block

    __half* B16; cudaGetSymbolAddress((void**)&B16, g_B16);
    float*  A;   cudaGetSymbolAddress((void**)&A, g_bufA);

    const float* feat_in = x;
    const float* biases[3]  = {b1, b2, b3};
    const float* weights[3] = {W1, W2, W3};

    for (int l = 0; l < 3; l++) {
        gemm128_kernel<<<gemm_blocks, 256, GEMM_SMEM>>>(feat_in, weights[l], B16, N_NODES);
        gather_kernel<<<node_warp_blocks, 256>>>(biases[l]);
        feat_in = A;
    }

    zero_pool_kernel<<<1, 256>>>();
    pool_kernel<<<node_warp_blocks, 256>>>(bat);
    final_kernel<<<N_GRAPHS, 32>>>(Wl, bl, out);
}